// round 9
// baseline (speedup 1.0000x reference)
#include <cuda_runtime.h>
#include <cuda_bf16.h>
#include <math.h>

// Problem constants
static constexpr int   N_NODES  = 200000;
static constexpr int   N_USERS  = 100000;
static constexpr int   DIM      = 64;
static constexpr int   LAYERS   = 3;
static constexpr int   E_EDGES  = 3000000;
static constexpr int   N_LINK   = 100000;
static constexpr int   EMB_COLS = (LAYERS + 1) * DIM;             // 256
static constexpr int   CSR_CAP  = E_EDGES + 16 * N_NODES + 64;    // 16-padded capacity

// ---------------------------------------------------------------------------
// Scratch. Feature tables have a ZERO GUARD ROW at index 0 (node v -> row v+1).
// Guard rows are never written (zero from .bss forever). CSR entries store
// (src+1); padding entries are 0 and gather the guard row (adds 0.0, L1-hot).
// deg/csr/totals are re-zeroed by k_tail at the END of each call so every
// call sees identical state and does identical work.
// ---------------------------------------------------------------------------
__device__ int   g_deg_s[N_NODES],  g_deg_t[N_NODES];
__device__ int2  g_seg_s[N_NODES],  g_seg_t[N_NODES];   // {start, deg}
__device__ int   g_cur_s[N_NODES],  g_cur_t[N_NODES];
__device__ int   g_tot_s,           g_tot_t;
__device__ int   g_csr_s[CSR_CAP],  g_csr_t[CSR_CAP];
__device__ float g_invdeg_s[N_NODES], g_invdeg_t[N_NODES];
__device__ float g_means[(size_t)(N_NODES + 1) * DIM];       // +guard
__device__ float g_meant[(size_t)(N_NODES + 1) * DIM];       // +guard
__device__ float g_xt   [(size_t)(N_NODES + 1) * DIM];       // +guard
__device__ float g_embs [(size_t)(N_NODES + 1) * EMB_COLS];  // +guard

// ---------------------------------------------------------------------------
// (1) Histogram degrees for both graphs (deg arrays are pre-zeroed).
// ---------------------------------------------------------------------------
__global__ void k_hist(const int* __restrict__ s_dst, const int* __restrict__ t_dst) {
    int e = blockIdx.x * blockDim.x + threadIdx.x;
    if (e < E_EDGES) {
        atomicAdd(&g_deg_s[s_dst[e]], 1);
        atomicAdd(&g_deg_t[t_dst[e]], 1);
    }
}

// ---------------------------------------------------------------------------
// (2) Claim 16-padded CSR segments via atomic cursor (segment order is
// irrelevant for a gather). Also: invdeg + copy emb into g_embs block 0.
// ---------------------------------------------------------------------------
__global__ void k_offsets(const float4* __restrict__ emb4) {
    int stride = gridDim.x * blockDim.x;
    int t0 = blockIdx.x * blockDim.x + threadIdx.x;

    for (int i = t0; i < N_NODES; i += stride) {
        int ds = g_deg_s[i], dt = g_deg_t[i];
        int ps = (ds + 15) & ~15, pt = (dt + 15) & ~15;
        int rs = atomicAdd(&g_tot_s, ps);
        int rt = atomicAdd(&g_tot_t, pt);
        g_seg_s[i] = make_int2(rs, ds);  g_cur_s[i] = rs;
        g_seg_t[i] = make_int2(rt, dt);  g_cur_t[i] = rt;
        g_invdeg_s[i] = 1.f / fmaxf((float)ds, 1.f);
        g_invdeg_t[i] = 1.f / fmaxf((float)dt, 1.f);
    }
    // copy emb -> g_embs rows 1..N, columns [0,64)
    const long NF4 = (long)N_NODES * (DIM / 4);
    for (long i = t0; i < NF4; i += stride) {
        long v = i >> 4;                // node (0-based)
        int  d = (int)(i & 15);
        reinterpret_cast<float4*>(g_embs)[(v + 1) * (EMB_COLS / 4) + d] = emb4[i];
    }
}

// ---------------------------------------------------------------------------
// (3) Fill CSR: store src+1 (0 is reserved for the zero guard row).
// ---------------------------------------------------------------------------
__global__ void k_fill(const int* __restrict__ s_src, const int* __restrict__ s_dst,
                       const int* __restrict__ t_src, const int* __restrict__ t_dst) {
    int e = blockIdx.x * blockDim.x + threadIdx.x;
    if (e < E_EDGES) {
        int ps = atomicAdd(&g_cur_s[s_dst[e]], 1);
        g_csr_s[ps] = s_src[e] + 1;
        int pt = atomicAdd(&g_cur_t[t_dst[e]], 1);
        g_csr_t[pt] = t_src[e] + 1;
    }
}

// ---------------------------------------------------------------------------
// (4..) Gather conv: HALF-WARP per node, float4 (LDG.128) lanes.
// Rows padded to multiple of 16 -> most nodes (avg deg 15) are ONE branch-free
// group: 1 LDG.32 (csr, 16 entries across the half-warp's lanes) then 16
// independent LDG.128 gathers in flight (MLP=16). Padding gathers hit the
// L1-resident guard row. Writes pre-scaled mean (1-based rows).
// ---------------------------------------------------------------------------
__global__ void __launch_bounds__(256)
k_conv(const float* __restrict__ x, int xstr,
       const int2* __restrict__ seg, const float* __restrict__ invd,
       const int* __restrict__ csr, float* __restrict__ om, int nN) {
    int w = (blockIdx.x * blockDim.x + threadIdx.x) >> 5;
    if (w >= nN / 2) return;
    int      lane = threadIdx.x & 31;
    int      h    = lane >> 4;                      // half-warp id
    int      c    = lane & 15;                      // float4 chunk / csr slot
    unsigned hm   = h ? 0xFFFF0000u : 0x0000FFFFu;
    int      v    = 2 * w + h;                      // 0-based node

    int2 sd   = __ldg(&seg[v]);                     // {start, deg} in one LDG.64
    int  start = sd.x;
    int  p16   = (sd.y + 15) & ~15;

    float4 acc = make_float4(0.f, 0.f, 0.f, 0.f);

    for (int j0 = 0; j0 < p16; j0 += 16) {
        int idx = __ldg(&csr[start + j0 + c]);      // 16 entries per half-warp
        #pragma unroll
        for (int j = 0; j < 16; j++) {
            int s = __shfl_sync(hm, idx, h * 16 + j);
            float4 vv = __ldg(reinterpret_cast<const float4*>(
                                  x + (size_t)s * xstr) + c);
            acc.x += vv.x; acc.y += vv.y; acc.z += vv.z; acc.w += vv.w;
        }
    }

    float iv = invd[v];
    float4 o = make_float4(acc.x * iv, acc.y * iv, acc.z * iv, acc.w * iv);
    reinterpret_cast<float4*>(om + (size_t)(v + 1) * DIM)[c] = o;
}

// ---------------------------------------------------------------------------
// Combine: users get mix GEMM ue=[ms|mt]@W^T+b; write source slice into
// g_embs(layer+1); write target into g_xt unless last layer. 1-based rows.
// ---------------------------------------------------------------------------
__global__ void __launch_bounds__(256)
k_combine(const float* __restrict__ mix_w, const float* __restrict__ mix_b,
          int layer, int write_xt) {
    __shared__ float WT[128 * 64];   // WT[k*64 + d] = W[d,k]
    __shared__ float BB[64];

    const float* W = mix_w + (size_t)layer * 64 * 128;
    for (int i = threadIdx.x; i < 64 * 128; i += blockDim.x) {
        int k = i >> 6, d = i & 63;
        WT[i] = W[d * 128 + k];
    }
    if (threadIdx.x < 64) BB[threadIdx.x] = mix_b[layer * 64 + threadIdx.x];
    __syncthreads();

    int lane = threadIdx.x & 31;
    int warp = threadIdx.x >> 5;
    int wpb  = blockDim.x >> 5;

    for (int v = blockIdx.x * wpb + warp; v < N_NODES; v += gridDim.x * wpb) {
        size_t base = (size_t)(v + 1) * DIM;

        float ms0 = g_means[base + lane];
        float ms1 = g_means[base + 32 + lane];
        float mt0 = g_meant[base + lane];
        float mt1 = g_meant[base + 32 + lane];

        float o0, o1, t0, t1;
        if (v < N_USERS) {
            float a0 = BB[lane], a1 = BB[lane + 32];
            #pragma unroll
            for (int k = 0; k < 32; k++) {
                float m = __shfl_sync(0xffffffffu, ms0, k);
                a0 += m * WT[k * 64 + lane];
                a1 += m * WT[k * 64 + lane + 32];
            }
            #pragma unroll
            for (int k = 0; k < 32; k++) {
                float m = __shfl_sync(0xffffffffu, ms1, k);
                a0 += m * WT[(k + 32) * 64 + lane];
                a1 += m * WT[(k + 32) * 64 + lane + 32];
            }
            #pragma unroll
            for (int k = 0; k < 32; k++) {
                float m = __shfl_sync(0xffffffffu, mt0, k);
                a0 += m * WT[(k + 64) * 64 + lane];
                a1 += m * WT[(k + 64) * 64 + lane + 32];
            }
            #pragma unroll
            for (int k = 0; k < 32; k++) {
                float m = __shfl_sync(0xffffffffu, mt1, k);
                a0 += m * WT[(k + 96) * 64 + lane];
                a1 += m * WT[(k + 96) * 64 + lane + 32];
            }
            o0 = a0; o1 = a1; t0 = a0; t1 = a1;
        } else {
            o0 = ms0; o1 = ms1; t0 = mt0; t1 = mt1;
        }

        if (write_xt) {
            g_xt[base + lane]      = t0;
            g_xt[base + 32 + lane] = t1;
        }
        float* er = g_embs + (size_t)(v + 1) * EMB_COLS + (size_t)(layer + 1) * DIM;
        er[lane]      = o0;
        er[lane + 32] = o1;
    }
}

// ---------------------------------------------------------------------------
// Prediction head: warp per link (1-based rows).
// ---------------------------------------------------------------------------
__global__ void k_pred(const int* __restrict__ link,
                       const float* __restrict__ pred_w,
                       const float* __restrict__ pred_b,
                       float* __restrict__ out) {
    __shared__ float pw[512];
    for (int i = threadIdx.x; i < 512; i += blockDim.x) pw[i] = pred_w[i];
    __syncthreads();

    int lane = threadIdx.x & 31;
    int warp = threadIdx.x >> 5;
    int j = blockIdx.x * (blockDim.x >> 5) + warp;
    if (j >= N_LINK) return;

    int u  = __ldg(&link[j]) + 1;
    int it = __ldg(&link[N_LINK + j]) + 1;
    const float* ue = g_embs + (size_t)u  * EMB_COLS;
    const float* ie = g_embs + (size_t)it * EMB_COLS;

    float acc = 0.f;
    #pragma unroll
    for (int c = 0; c < 8; c++) acc += ue[lane + c * 32] * pw[lane + c * 32];
    #pragma unroll
    for (int c = 0; c < 8; c++) acc += ie[lane + c * 32] * pw[256 + lane + c * 32];

    #pragma unroll
    for (int o = 16; o > 0; o >>= 1) acc += __shfl_down_sync(0xffffffffu, acc, o);

    if (lane == 0) {
        float z = acc + pred_b[0];
        z = (z >= 0.f) ? z : 0.01f * z;
        out[j] = 1.f / (1.f + expf(-z));
    }
}

// ---------------------------------------------------------------------------
// Tail: restore the zero state (deg, totals, csr) for the next call.
// ---------------------------------------------------------------------------
__global__ void k_tail() {
    int stride = gridDim.x * blockDim.x;
    int t0 = blockIdx.x * blockDim.x + threadIdx.x;
    for (int i = t0; i < CSR_CAP; i += stride) { g_csr_s[i] = 0; g_csr_t[i] = 0; }
    for (int i = t0; i < N_NODES; i += stride) { g_deg_s[i] = 0; g_deg_t[i] = 0; }
    if (t0 == 0) { g_tot_s = 0; g_tot_t = 0; }
}

// ---------------------------------------------------------------------------
// Launch. First 3 launches are CSR build; convs follow (ncu capture slot).
// ---------------------------------------------------------------------------
extern "C" void kernel_launch(void* const* d_in, const int* in_sizes, int n_in,
                              void* d_out, int out_size) {
    const int*   sei    = (const int*)  d_in[0];
    const int*   tei    = (const int*)  d_in[1];
    const int*   link   = (const int*)  d_in[2];
    const float* emb    = (const float*)d_in[3];
    const float* mix_w  = (const float*)d_in[4];
    const float* mix_b  = (const float*)d_in[5];
    const float* pred_w = (const float*)d_in[6];
    const float* pred_b = (const float*)d_in[7];
    float*       out    = (float*)d_out;

    const int* s_src = sei;
    const int* s_dst = sei + E_EDGES;
    const int* t_src = tei;
    const int* t_dst = tei + E_EDGES;

    k_hist   <<<(E_EDGES + 255) / 256, 256>>>(s_dst, t_dst);
    k_offsets<<<4096, 256>>>(reinterpret_cast<const float4*>(emb));
    k_fill   <<<(E_EDGES + 255) / 256, 256>>>(s_src, s_dst, t_src, t_dst);

    for (int l = 0; l < LAYERS; l++) {
        // source conv (reads g_embs slice l, stride 256)
        k_conv<<<(N_NODES / 2 * 32 + 255) / 256, 256>>>(
            g_embs + (size_t)l * DIM, EMB_COLS,
            g_seg_s, g_invdeg_s, g_csr_s, g_means, N_NODES);
        // target conv: layer0 reads g_embs slice 0; layers>=1 read g_xt.
        // Last layer: only user rows are ever consumed.
        const float* xt  = (l == 0) ? g_embs : g_xt;
        int          xts = (l == 0) ? EMB_COLS : DIM;
        int          nT  = (l == LAYERS - 1) ? N_USERS : N_NODES;
        k_conv<<<(nT / 2 * 32 + 255) / 256, 256>>>(
            xt, xts, g_seg_t, g_invdeg_t, g_csr_t, g_meant, nT);

        k_combine<<<2960, 256>>>(mix_w, mix_b, l, l < LAYERS - 1 ? 1 : 0);
    }

    k_pred<<<(N_LINK + 7) / 8, 256>>>(link, pred_w, pred_b, out);
    k_tail<<<4096, 256>>>();
}

// round 10
// speedup vs baseline: 1.0114x; 1.0114x over previous
#include <cuda_runtime.h>
#include <cuda_bf16.h>
#include <math.h>

// Problem constants
static constexpr int   N_NODES  = 200000;
static constexpr int   N_USERS  = 100000;
static constexpr int   DIM      = 64;
static constexpr int   LAYERS   = 3;
static constexpr int   E_EDGES  = 3000000;
static constexpr int   N_LINK   = 100000;
static constexpr int   EMB_COLS = (LAYERS + 1) * DIM;             // 256
static constexpr int   CSR_CAP  = E_EDGES + 16 * N_NODES + 64;    // 16-padded capacity

// ---------------------------------------------------------------------------
// Scratch. Feature tables have a ZERO GUARD ROW at index 0 (node v -> row v+1).
// Guard rows are never written (zero from .bss forever). CSR entries store
// (src+1); padding entries are 0 and gather the guard row (adds 0.0, L1-hot).
// deg/csr/totals are re-zeroed by k_tail at the END of each call so every
// call sees identical state and does identical work.
// ---------------------------------------------------------------------------
__device__ int   g_deg_s[N_NODES],  g_deg_t[N_NODES];
__device__ int2  g_seg_s[N_NODES],  g_seg_t[N_NODES];   // {start, deg}
__device__ int   g_cur_s[N_NODES],  g_cur_t[N_NODES];
__device__ int   g_tot_s,           g_tot_t;
__device__ int   g_csr_s[CSR_CAP],  g_csr_t[CSR_CAP];
__device__ float g_invdeg_s[N_NODES], g_invdeg_t[N_NODES];
__device__ float g_means[(size_t)(N_NODES + 1) * DIM];       // +guard
__device__ float g_meant[(size_t)(N_NODES + 1) * DIM];       // +guard
__device__ float g_xt   [(size_t)(N_NODES + 1) * DIM];       // +guard
__device__ float g_embs [(size_t)(N_NODES + 1) * EMB_COLS];  // +guard

// ---------------------------------------------------------------------------
// (1) Histogram degrees for both graphs (deg arrays are pre-zeroed).
// ---------------------------------------------------------------------------
__global__ void k_hist(const int* __restrict__ s_dst, const int* __restrict__ t_dst) {
    int e = blockIdx.x * blockDim.x + threadIdx.x;
    if (e < E_EDGES) {
        atomicAdd(&g_deg_s[s_dst[e]], 1);
        atomicAdd(&g_deg_t[t_dst[e]], 1);
    }
}

// ---------------------------------------------------------------------------
// (2) Claim 16-padded CSR segments. Block-aggregated: 256-wide shared-mem
// scan, then ONE atomicAdd per block per graph (was: one per node ->
// 400k same-address atomics serialized at a single LTS slice).
// Also: invdeg + copy emb into g_embs column block 0.
// ---------------------------------------------------------------------------
__global__ void k_offsets(const float4* __restrict__ emb4) {
    __shared__ int sh_s[256], sh_t[256];
    __shared__ int base_s, base_t;
    int t = threadIdx.x;
    int i = blockIdx.x * 256 + t;

    int ds = 0, dt = 0;
    if (i < N_NODES) { ds = g_deg_s[i]; dt = g_deg_t[i]; }
    int ps = (ds + 15) & ~15, pt = (dt + 15) & ~15;
    sh_s[t] = ps; sh_t[t] = pt;
    __syncthreads();
    #pragma unroll
    for (int off = 1; off < 256; off <<= 1) {
        int a = (t >= off) ? sh_s[t - off] : 0;
        int b = (t >= off) ? sh_t[t - off] : 0;
        __syncthreads();
        sh_s[t] += a; sh_t[t] += b;
        __syncthreads();
    }
    if (t == 255) {
        base_s = atomicAdd(&g_tot_s, sh_s[255]);
        base_t = atomicAdd(&g_tot_t, sh_t[255]);
    }
    __syncthreads();
    if (i < N_NODES) {
        int rs = base_s + sh_s[t] - ps;          // exclusive within block
        int rt = base_t + sh_t[t] - pt;
        g_seg_s[i] = make_int2(rs, ds);  g_cur_s[i] = rs;
        g_seg_t[i] = make_int2(rt, dt);  g_cur_t[i] = rt;
        g_invdeg_s[i] = 1.f / fmaxf((float)ds, 1.f);
        g_invdeg_t[i] = 1.f / fmaxf((float)dt, 1.f);
    }
    // copy emb -> g_embs rows 1..N, columns [0,64)
    const long NF4 = (long)N_NODES * (DIM / 4);
    long stride = (long)gridDim.x * blockDim.x;
    for (long j = (long)blockIdx.x * 256 + t; j < NF4; j += stride) {
        long v = j >> 4;
        int  d = (int)(j & 15);
        reinterpret_cast<float4*>(g_embs)[(v + 1) * (EMB_COLS / 4) + d] = emb4[j];
    }
}

// ---------------------------------------------------------------------------
// (3) Fill CSR: store src+1 (0 is reserved for the zero guard row).
// ---------------------------------------------------------------------------
__global__ void k_fill(const int* __restrict__ s_src, const int* __restrict__ s_dst,
                       const int* __restrict__ t_src, const int* __restrict__ t_dst) {
    int e = blockIdx.x * blockDim.x + threadIdx.x;
    if (e < E_EDGES) {
        int ps = atomicAdd(&g_cur_s[s_dst[e]], 1);
        g_csr_s[ps] = s_src[e] + 1;
        int pt = atomicAdd(&g_cur_t[t_dst[e]], 1);
        g_csr_t[pt] = t_src[e] + 1;
    }
}

// ---------------------------------------------------------------------------
// (4..) Gather conv: HALF-WARP per node, float4 (LDG.128) lanes.
// Rows padded to 16 -> most nodes are ONE branch-free group: 1 csr LDG.32
// then 16 independent LDG.128 gathers. min 6 blocks/SM for occupancy/MLP.
// ---------------------------------------------------------------------------
__global__ void __launch_bounds__(256, 6)
k_conv(const float* __restrict__ x, int xstr,
       const int2* __restrict__ seg, const float* __restrict__ invd,
       const int* __restrict__ csr, float* __restrict__ om, int nN) {
    int w = (blockIdx.x * blockDim.x + threadIdx.x) >> 5;
    if (w >= nN / 2) return;
    int      lane = threadIdx.x & 31;
    int      h    = lane >> 4;                      // half-warp id
    int      c    = lane & 15;                      // float4 chunk / csr slot
    unsigned hm   = h ? 0xFFFF0000u : 0x0000FFFFu;
    int      v    = 2 * w + h;                      // 0-based node

    int2 sd    = __ldg(&seg[v]);                    // {start, deg}
    int  start = sd.x;
    int  p16   = (sd.y + 15) & ~15;

    float4 acc = make_float4(0.f, 0.f, 0.f, 0.f);

    for (int j0 = 0; j0 < p16; j0 += 16) {
        int idx = __ldg(&csr[start + j0 + c]);      // 16 entries per half-warp
        #pragma unroll
        for (int j = 0; j < 16; j++) {
            int s = __shfl_sync(hm, idx, h * 16 + j);
            float4 vv = __ldg(reinterpret_cast<const float4*>(
                                  x + (size_t)s * xstr) + c);
            acc.x += vv.x; acc.y += vv.y; acc.z += vv.z; acc.w += vv.w;
        }
    }

    float iv = invd[v];
    float4 o = make_float4(acc.x * iv, acc.y * iv, acc.z * iv, acc.w * iv);
    reinterpret_cast<float4*>(om + (size_t)(v + 1) * DIM)[c] = o;
}

// ---------------------------------------------------------------------------
// Combine: users get mix GEMM ue=[ms|mt]@W^T+b. W repacked in smem as float4
// (k-pairs x output-pairs) -> 64 LDS.128 per user instead of 256 LDS.32.
// Writes source slice into g_embs(layer+1); target into g_xt unless last.
// ---------------------------------------------------------------------------
__global__ void __launch_bounds__(256)
k_combine(const float* __restrict__ mix_w, const float* __restrict__ mix_b,
          int layer, int write_xt) {
    // WT4[k2*32 + ln] = { W[ln][2k2], W[ln+32][2k2], W[ln][2k2+1], W[ln+32][2k2+1] }
    __shared__ float4 WT4[64 * 32];    // 32 KB
    __shared__ float  BB[64];

    const float* W = mix_w + (size_t)layer * 64 * 128;
    for (int i = threadIdx.x; i < 64 * 32; i += blockDim.x) {
        int k2 = i >> 5, ln = i & 31;
        WT4[i] = make_float4(W[ln * 128 + 2 * k2],       W[(ln + 32) * 128 + 2 * k2],
                             W[ln * 128 + 2 * k2 + 1],   W[(ln + 32) * 128 + 2 * k2 + 1]);
    }
    if (threadIdx.x < 64) BB[threadIdx.x] = mix_b[layer * 64 + threadIdx.x];
    __syncthreads();

    int lane = threadIdx.x & 31;
    int warp = threadIdx.x >> 5;
    int wpb  = blockDim.x >> 5;

    for (int v = blockIdx.x * wpb + warp; v < N_NODES; v += gridDim.x * wpb) {
        size_t base = (size_t)(v + 1) * DIM;

        float ms0 = g_means[base + lane];
        float ms1 = g_means[base + 32 + lane];
        float mt0 = g_meant[base + lane];
        float mt1 = g_meant[base + 32 + lane];

        float o0, o1, t0, t1;
        if (v < N_USERS) {
            float a0 = BB[lane], a1 = BB[lane + 32];
            #pragma unroll
            for (int k2 = 0; k2 < 16; k2++) {           // k block 0: ms0
                float m0 = __shfl_sync(0xffffffffu, ms0, 2 * k2);
                float m1 = __shfl_sync(0xffffffffu, ms0, 2 * k2 + 1);
                float4 q = WT4[k2 * 32 + lane];
                a0 += m0 * q.x + m1 * q.z;
                a1 += m0 * q.y + m1 * q.w;
            }
            #pragma unroll
            for (int k2 = 0; k2 < 16; k2++) {           // k block 1: ms1
                float m0 = __shfl_sync(0xffffffffu, ms1, 2 * k2);
                float m1 = __shfl_sync(0xffffffffu, ms1, 2 * k2 + 1);
                float4 q = WT4[(16 + k2) * 32 + lane];
                a0 += m0 * q.x + m1 * q.z;
                a1 += m0 * q.y + m1 * q.w;
            }
            #pragma unroll
            for (int k2 = 0; k2 < 16; k2++) {           // k block 2: mt0
                float m0 = __shfl_sync(0xffffffffu, mt0, 2 * k2);
                float m1 = __shfl_sync(0xffffffffu, mt0, 2 * k2 + 1);
                float4 q = WT4[(32 + k2) * 32 + lane];
                a0 += m0 * q.x + m1 * q.z;
                a1 += m0 * q.y + m1 * q.w;
            }
            #pragma unroll
            for (int k2 = 0; k2 < 16; k2++) {           // k block 3: mt1
                float m0 = __shfl_sync(0xffffffffu, mt1, 2 * k2);
                float m1 = __shfl_sync(0xffffffffu, mt1, 2 * k2 + 1);
                float4 q = WT4[(48 + k2) * 32 + lane];
                a0 += m0 * q.x + m1 * q.z;
                a1 += m0 * q.y + m1 * q.w;
            }
            o0 = a0; o1 = a1; t0 = a0; t1 = a1;
        } else {
            o0 = ms0; o1 = ms1; t0 = mt0; t1 = mt1;
        }

        if (write_xt) {
            g_xt[base + lane]      = t0;
            g_xt[base + 32 + lane] = t1;
        }
        float* er = g_embs + (size_t)(v + 1) * EMB_COLS + (size_t)(layer + 1) * DIM;
        er[lane]      = o0;
        er[lane + 32] = o1;
    }
}

// ---------------------------------------------------------------------------
// Prediction head: warp per link, float4 loads (1-based rows).
// ---------------------------------------------------------------------------
__global__ void k_pred(const int* __restrict__ link,
                       const float* __restrict__ pred_w,
                       const float* __restrict__ pred_b,
                       float* __restrict__ out) {
    __shared__ float4 pw4[128];                       // 512 floats
    for (int i = threadIdx.x; i < 128; i += blockDim.x)
        pw4[i] = reinterpret_cast<const float4*>(pred_w)[i];
    __syncthreads();

    int lane = threadIdx.x & 31;
    int warp = threadIdx.x >> 5;
    int j = blockIdx.x * (blockDim.x >> 5) + warp;
    if (j >= N_LINK) return;

    int u  = __ldg(&link[j]) + 1;
    int it = __ldg(&link[N_LINK + j]) + 1;
    const float4* ue4 = reinterpret_cast<const float4*>(g_embs + (size_t)u  * EMB_COLS);
    const float4* ie4 = reinterpret_cast<const float4*>(g_embs + (size_t)it * EMB_COLS);

    float acc = 0.f;
    #pragma unroll
    for (int r = 0; r < 2; r++) {
        int idx = lane + r * 32;                      // 0..63
        float4 a = __ldg(&ue4[idx]);
        float4 w = pw4[idx];
        acc += a.x * w.x + a.y * w.y + a.z * w.z + a.w * w.w;
        float4 b = __ldg(&ie4[idx]);
        float4 w2 = pw4[64 + idx];
        acc += b.x * w2.x + b.y * w2.y + b.z * w2.z + b.w * w2.w;
    }

    #pragma unroll
    for (int o = 16; o > 0; o >>= 1) acc += __shfl_down_sync(0xffffffffu, acc, o);

    if (lane == 0) {
        float z = acc + pred_b[0];
        z = (z >= 0.f) ? z : 0.01f * z;
        out[j] = 1.f / (1.f + expf(-z));
    }
}

// ---------------------------------------------------------------------------
// Tail: restore the zero state (deg, totals, csr) for the next call.
// ---------------------------------------------------------------------------
__global__ void k_tail() {
    int stride = gridDim.x * blockDim.x;
    int t0 = blockIdx.x * blockDim.x + threadIdx.x;
    for (int i = t0; i < CSR_CAP; i += stride) { g_csr_s[i] = 0; g_csr_t[i] = 0; }
    for (int i = t0; i < N_NODES; i += stride) { g_deg_s[i] = 0; g_deg_t[i] = 0; }
    if (t0 == 0) { g_tot_s = 0; g_tot_t = 0; }
}

// ---------------------------------------------------------------------------
// Launch. First 3 launches are CSR build; convs follow (ncu capture slot).
// ---------------------------------------------------------------------------
extern "C" void kernel_launch(void* const* d_in, const int* in_sizes, int n_in,
                              void* d_out, int out_size) {
    const int*   sei    = (const int*)  d_in[0];
    const int*   tei    = (const int*)  d_in[1];
    const int*   link   = (const int*)  d_in[2];
    const float* emb    = (const float*)d_in[3];
    const float* mix_w  = (const float*)d_in[4];
    const float* mix_b  = (const float*)d_in[5];
    const float* pred_w = (const float*)d_in[6];
    const float* pred_b = (const float*)d_in[7];
    float*       out    = (float*)d_out;

    const int* s_src = sei;
    const int* s_dst = sei + E_EDGES;
    const int* t_src = tei;
    const int* t_dst = tei + E_EDGES;

    k_hist   <<<(E_EDGES + 255) / 256, 256>>>(s_dst, t_dst);
    k_offsets<<<(N_NODES + 255) / 256, 256>>>(reinterpret_cast<const float4*>(emb));
    k_fill   <<<(E_EDGES + 255) / 256, 256>>>(s_src, s_dst, t_src, t_dst);

    for (int l = 0; l < LAYERS; l++) {
        // source conv (reads g_embs slice l, stride 256)
        k_conv<<<(N_NODES / 2 * 32 + 255) / 256, 256>>>(
            g_embs + (size_t)l * DIM, EMB_COLS,
            g_seg_s, g_invdeg_s, g_csr_s, g_means, N_NODES);
        // target conv: layer0 reads g_embs slice 0; layers>=1 read g_xt.
        // Last layer: only user rows are ever consumed.
        const float* xt  = (l == 0) ? g_embs : g_xt;
        int          xts = (l == 0) ? EMB_COLS : DIM;
        int          nT  = (l == LAYERS - 1) ? N_USERS : N_NODES;
        k_conv<<<(nT / 2 * 32 + 255) / 256, 256>>>(
            xt, xts, g_seg_t, g_invdeg_t, g_csr_t, g_meant, nT);

        k_combine<<<2960, 256>>>(mix_w, mix_b, l, l < LAYERS - 1 ? 1 : 0);
    }

    k_pred<<<(N_LINK + 7) / 8, 256>>>(link, pred_w, pred_b, out);
    k_tail<<<4096, 256>>>();
}